// round 2
// baseline (speedup 1.0000x reference)
#include <cuda_runtime.h>
#include <cstdint>
#include <float.h>

#define N_NODES 100000
#define N_EDGES 2000000
#define HID 32
#define NCLS 40

// ---------------- scratch (static device memory; no allocation) ----------------
__device__ float g_h1 [N_NODES * HID];   // layer1 projected node state (GRU h input)
__device__ float g_m1 [N_NODES * HID];   // layer1 message vectors
__device__ float g_agg1[N_NODES * HID];  // layer1 scatter-add accumulator
__device__ float g_hr [N_NODES * HID];   // relu(gru1 output)
__device__ float g_h2 [N_NODES * NCLS];  // layer2 projected node state
__device__ float g_m2 [N_NODES * NCLS];  // layer2 message vectors
__device__ float g_agg2[N_NODES * NCLS]; // layer2 scatter-add accumulator

// ---------------- K1: h1 = x@W1p, m1 = h1@W1m, zero agg1 ----------------
// warp per node, lane = output column, shuffles broadcast the input row.
__global__ void k_proj1(const float* __restrict__ x,
                        const float* __restrict__ Wp,
                        const float* __restrict__ Wm) {
    __shared__ float sWp[32 * 32];
    __shared__ float sWm[32 * 32];
    int t = threadIdx.x;
    for (int i = t; i < 1024; i += 256) { sWp[i] = Wp[i]; sWm[i] = Wm[i]; }
    __syncthreads();

    int node = blockIdx.x * 8 + (t >> 5);
    if (node >= N_NODES) return;
    int lane = t & 31;
    float xv = x[node * 32 + lane];
    float h = 0.f;
#pragma unroll
    for (int k = 0; k < 32; k++)
        h = fmaf(__shfl_sync(0xffffffffu, xv, k), sWp[k * 32 + lane], h);
    float m = 0.f;
#pragma unroll
    for (int k = 0; k < 32; k++)
        m = fmaf(__shfl_sync(0xffffffffu, h, k), sWm[k * 32 + lane], m);
    int idx = node * 32 + lane;
    g_h1[idx]   = h;
    g_m1[idx]   = m;
    g_agg1[idx] = 0.f;
}

// ---------------- K2: edge scatter layer 1 (warp per edge, 32 cols) ----------------
__global__ void k_edge1(const int* __restrict__ ei,
                        const float* __restrict__ ew) {
    long long tid = (long long)blockIdx.x * blockDim.x + threadIdx.x;
    int e = (int)(tid >> 5);
    if (e >= N_EDGES) return;
    int c = (int)(tid & 31);
    int src = ei[e];
    int dst = ei[N_EDGES + e];
    float v = g_m1[src * 32 + c] * ew[e];
    atomicAdd(&g_agg1[dst * 32 + c], v);
}

// ---------------- K3: GRU cell layer 1 + ReLU ----------------
// warp per node; weights transposed in shared with +1 padding (bank-conflict free).
__global__ void k_gru1(const float* __restrict__ wih,
                       const float* __restrict__ whh,
                       const float* __restrict__ bih,
                       const float* __restrict__ bhh) {
    __shared__ float sWi[32 * 97]; // [k][r], r in 0..95
    __shared__ float sWh[32 * 97];
    int t = threadIdx.x;
    for (int i = t; i < 96 * 32; i += 256) {
        int r = i >> 5, k = i & 31;
        sWi[k * 97 + r] = wih[i];
        sWh[k * 97 + r] = whh[i];
    }
    __syncthreads();

    int node = blockIdx.x * 8 + (t >> 5);
    if (node >= N_NODES) return;
    int lane = t & 31;
    int idx = node * 32 + lane;
    float a  = g_agg1[idx];
    float hv = g_h1[idx];

    float gir = bih[lane], giz = bih[32 + lane], gin = bih[64 + lane];
    float ghr = bhh[lane], ghz = bhh[32 + lane], ghn = bhh[64 + lane];
#pragma unroll
    for (int k = 0; k < 32; k++) {
        float ak = __shfl_sync(0xffffffffu, a,  k);
        float hk = __shfl_sync(0xffffffffu, hv, k);
        const float* wi = &sWi[k * 97];
        const float* wh = &sWh[k * 97];
        gir = fmaf(ak, wi[lane],      gir);
        giz = fmaf(ak, wi[32 + lane], giz);
        gin = fmaf(ak, wi[64 + lane], gin);
        ghr = fmaf(hk, wh[lane],      ghr);
        ghz = fmaf(hk, wh[32 + lane], ghz);
        ghn = fmaf(hk, wh[64 + lane], ghn);
    }
    float r = 1.f / (1.f + __expf(-(gir + ghr)));
    float z = 1.f / (1.f + __expf(-(giz + ghz)));
    float n = tanhf(gin + r * ghn);
    float hnew = (1.f - z) * n + z * hv;
    g_hr[idx] = fmaxf(hnew, 0.f);
}

// ---------------- K4: h2 = hr@W2p (32->40), m2 = h2@W2m (40->40), zero agg2 ----------
// warp per node: lane owns col `lane`, lanes 0..7 also own col 32+lane.
__global__ void k_proj2(const float* __restrict__ Wp,
                        const float* __restrict__ Wm) {
    __shared__ float sWp[32 * 40];
    __shared__ float sWm[40 * 40];
    int t = threadIdx.x;
    for (int i = t; i < 32 * 40; i += 256) sWp[i] = Wp[i];
    for (int i = t; i < 40 * 40; i += 256) sWm[i] = Wm[i];
    __syncthreads();

    int node = blockIdx.x * 8 + (t >> 5);
    if (node >= N_NODES) return;
    int lane = t & 31;
    int c2 = 32 + (lane & 7);      // always-valid high column index
    float a = g_hr[node * 32 + lane];

    float h_lo = 0.f, h_hi = 0.f;
#pragma unroll
    for (int k = 0; k < 32; k++) {
        float ak = __shfl_sync(0xffffffffu, a, k);
        h_lo = fmaf(ak, sWp[k * 40 + lane], h_lo);
        h_hi = fmaf(ak, sWp[k * 40 + c2],   h_hi);
    }
    float m_lo = 0.f, m_hi = 0.f;
#pragma unroll
    for (int k = 0; k < 32; k++) {
        float hk = __shfl_sync(0xffffffffu, h_lo, k);
        m_lo = fmaf(hk, sWm[k * 40 + lane], m_lo);
        m_hi = fmaf(hk, sWm[k * 40 + c2],   m_hi);
    }
#pragma unroll
    for (int k = 0; k < 8; k++) {
        float hk = __shfl_sync(0xffffffffu, h_hi, k);
        m_lo = fmaf(hk, sWm[(32 + k) * 40 + lane], m_lo);
        m_hi = fmaf(hk, sWm[(32 + k) * 40 + c2],   m_hi);
    }
    int base = node * 40;
    g_h2[base + lane] = h_lo;
    g_m2[base + lane] = m_lo;
    g_agg2[base + lane] = 0.f;
    if (lane < 8) {
        g_h2[base + 32 + lane] = h_hi;
        g_m2[base + 32 + lane] = m_hi;
        g_agg2[base + 32 + lane] = 0.f;
    }
}

// ---------------- K5: edge scatter layer 2 (40 threads per edge) ----------------
__global__ void k_edge2(const int* __restrict__ ei,
                        const float* __restrict__ ew) {
    int t = threadIdx.x;              // 320 threads = 8 edges * 40 cols
    int e = blockIdx.x * 8 + t / 40;
    if (e >= N_EDGES) return;
    int c = t % 40;
    int src = ei[e];
    int dst = ei[N_EDGES + e];
    float v = g_m2[src * 40 + c] * ew[e];
    atomicAdd(&g_agg2[dst * 40 + c], v);
}

// ---------------- K6: GRU cell layer 2 + log_softmax ----------------
__global__ void k_gru2(float* __restrict__ out,
                       const float* __restrict__ wih,
                       const float* __restrict__ whh,
                       const float* __restrict__ bih,
                       const float* __restrict__ bhh) {
    __shared__ float sWi[40 * 121]; // [k][r], r in 0..119, padded stride 121
    __shared__ float sWh[40 * 121];
    int t = threadIdx.x;
    for (int i = t; i < 120 * 40; i += 256) {
        int r = i / 40, k = i % 40;
        sWi[k * 121 + r] = wih[i];
        sWh[k * 121 + r] = whh[i];
    }
    __syncthreads();

    int node = blockIdx.x * 8 + (t >> 5);
    if (node >= N_NODES) return;
    int lane = t & 31;
    int c2 = 32 + (lane & 7);
    int b = node * 40;

    float a_lo = g_agg2[b + lane];
    float h_lo = g_h2[b + lane];
    float a_hi = (lane < 8) ? g_agg2[b + 32 + lane] : 0.f;
    float h_hi = (lane < 8) ? g_h2[b + 32 + lane]   : 0.f;

    float gir = bih[lane], giz = bih[40 + lane], gin = bih[80 + lane];
    float ghr = bhh[lane], ghz = bhh[40 + lane], ghn = bhh[80 + lane];
    float gir2 = bih[c2], giz2 = bih[40 + c2], gin2 = bih[80 + c2];
    float ghr2 = bhh[c2], ghz2 = bhh[40 + c2], ghn2 = bhh[80 + c2];

#pragma unroll
    for (int k = 0; k < 40; k++) {
        float ak = (k < 32) ? __shfl_sync(0xffffffffu, a_lo, k)
                            : __shfl_sync(0xffffffffu, a_hi, k - 32);
        float hk = (k < 32) ? __shfl_sync(0xffffffffu, h_lo, k)
                            : __shfl_sync(0xffffffffu, h_hi, k - 32);
        const float* wi = &sWi[k * 121];
        const float* wh = &sWh[k * 121];
        gir  = fmaf(ak, wi[lane],      gir);
        giz  = fmaf(ak, wi[40 + lane], giz);
        gin  = fmaf(ak, wi[80 + lane], gin);
        gir2 = fmaf(ak, wi[c2],        gir2);
        giz2 = fmaf(ak, wi[40 + c2],   giz2);
        gin2 = fmaf(ak, wi[80 + c2],   gin2);
        ghr  = fmaf(hk, wh[lane],      ghr);
        ghz  = fmaf(hk, wh[40 + lane], ghz);
        ghn  = fmaf(hk, wh[80 + lane], ghn);
        ghr2 = fmaf(hk, wh[c2],        ghr2);
        ghz2 = fmaf(hk, wh[40 + c2],   ghz2);
        ghn2 = fmaf(hk, wh[80 + c2],   ghn2);
    }

    float r1 = 1.f / (1.f + __expf(-(gir + ghr)));
    float z1 = 1.f / (1.f + __expf(-(giz + ghz)));
    float n1 = tanhf(gin + r1 * ghn);
    float v1 = (1.f - z1) * n1 + z1 * h_lo;

    float r2 = 1.f / (1.f + __expf(-(gir2 + ghr2)));
    float z2 = 1.f / (1.f + __expf(-(giz2 + ghz2)));
    float n2 = tanhf(gin2 + r2 * ghn2);
    float v2 = (1.f - z2) * n2 + z2 * h_hi;

    // log_softmax over the 40 values held by this warp
    float vmax = fmaxf(v1, (lane < 8) ? v2 : -FLT_MAX);
#pragma unroll
    for (int o = 16; o > 0; o >>= 1)
        vmax = fmaxf(vmax, __shfl_xor_sync(0xffffffffu, vmax, o));
    float se = __expf(v1 - vmax) + ((lane < 8) ? __expf(v2 - vmax) : 0.f);
#pragma unroll
    for (int o = 16; o > 0; o >>= 1)
        se += __shfl_xor_sync(0xffffffffu, se, o);
    float ls = vmax + logf(se);

    out[b + lane] = v1 - ls;
    if (lane < 8) out[b + 32 + lane] = v2 - ls;
}

// ---------------- launch ----------------
extern "C" void kernel_launch(void* const* d_in, const int* in_sizes, int n_in,
                              void* d_out, int out_size) {
    const float* x   = (const float*)d_in[0];
    const int*   ei  = (const int*)d_in[1];     // JAX x64 disabled -> int32
    const float* ew  = (const float*)d_in[2];
    const float* W1p = (const float*)d_in[3];
    const float* W1m = (const float*)d_in[4];
    const float* g1wih = (const float*)d_in[5];
    const float* g1whh = (const float*)d_in[6];
    const float* g1bih = (const float*)d_in[7];
    const float* g1bhh = (const float*)d_in[8];
    const float* W2p = (const float*)d_in[9];
    const float* W2m = (const float*)d_in[10];
    const float* g2wih = (const float*)d_in[11];
    const float* g2whh = (const float*)d_in[12];
    const float* g2bih = (const float*)d_in[13];
    const float* g2bhh = (const float*)d_in[14];
    float* out = (float*)d_out;

    int nodeBlocks = (N_NODES + 7) / 8;
    k_proj1<<<nodeBlocks, 256>>>(x, W1p, W1m);

    long long th1 = (long long)N_EDGES * 32;
    int eb1 = (int)((th1 + 255) / 256);
    k_edge1<<<eb1, 256>>>(ei, ew);

    k_gru1<<<nodeBlocks, 256>>>(g1wih, g1whh, g1bih, g1bhh);
    k_proj2<<<nodeBlocks, 256>>>(W2p, W2m);

    int eb2 = (N_EDGES + 7) / 8;
    k_edge2<<<eb2, 320>>>(ei, ew);

    k_gru2<<<nodeBlocks, 256>>>(out, g2wih, g2whh, g2bih, g2bhh);
}

// round 4
// speedup vs baseline: 1.4592x; 1.4592x over previous
#include <cuda_runtime.h>
#include <cstdint>
#include <float.h>

#define N_NODES 100000
#define N_EDGES 2000000
#define HID 32
#define NCLS 40

// ---------------- scratch (static device memory; no allocation) ----------------
__device__ float g_h1 [N_NODES * HID];
__device__ float g_m1 [N_NODES * HID];
__device__ float g_agg1[N_NODES * HID];
__device__ float g_h2 [N_NODES * NCLS];
__device__ float g_m2 [N_NODES * NCLS];
__device__ float g_agg2[N_NODES * NCLS];

__device__ __forceinline__ void red_add_v4(float* addr, float4 v) {
    asm volatile("red.global.add.v4.f32 [%0], {%1,%2,%3,%4};"
                 :: "l"(addr), "f"(v.x), "f"(v.y), "f"(v.z), "f"(v.w)
                 : "memory");
}

// ---------------- K1: h1 = x@W1p, m1 = h1@W1m, zero agg1 ----------------
__global__ void k_proj1(const float* __restrict__ x,
                        const float* __restrict__ Wp,
                        const float* __restrict__ Wm) {
    __shared__ float sWp[32 * 32];
    __shared__ float sWm[32 * 32];
    int t = threadIdx.x;
    for (int i = t; i < 1024; i += 256) { sWp[i] = Wp[i]; sWm[i] = Wm[i]; }
    __syncthreads();

    int node = blockIdx.x * 8 + (t >> 5);
    if (node >= N_NODES) return;
    int lane = t & 31;
    float xv = x[node * 32 + lane];
    float h = 0.f;
#pragma unroll
    for (int k = 0; k < 32; k++)
        h = fmaf(__shfl_sync(0xffffffffu, xv, k), sWp[k * 32 + lane], h);
    float m = 0.f;
#pragma unroll
    for (int k = 0; k < 32; k++)
        m = fmaf(__shfl_sync(0xffffffffu, h, k), sWm[k * 32 + lane], m);
    int idx = node * 32 + lane;
    g_h1[idx]   = h;
    g_m1[idx]   = m;
    g_agg1[idx] = 0.f;
}

// ---------------- K2: edge scatter layer 1 — 8 threads/edge, float4 + red.v4 ----
__global__ void k_edge1(const int* __restrict__ ei,
                        const float* __restrict__ ew) {
    long long tid = (long long)blockIdx.x * blockDim.x + threadIdx.x;
    int e = (int)(tid >> 3);
    if (e >= N_EDGES) return;
    int q = (int)(tid & 7);                 // which float4 chunk of 8
    int src = ei[e];
    int dst = ei[N_EDGES + e];
    float w = ew[e];
    const float4* mrow = (const float4*)&g_m1[src * 32];
    float4 m = mrow[q];
    m.x *= w; m.y *= w; m.z *= w; m.w *= w;
    red_add_v4(&g_agg1[dst * 32 + q * 4], m);
}

// ---------------- K3: GRU1 + ReLU + proj2 + msg2 (fused), zero agg2 ----------
__global__ void k_gru1_proj2(const float* __restrict__ wih,
                             const float* __restrict__ whh,
                             const float* __restrict__ bih,
                             const float* __restrict__ bhh,
                             const float* __restrict__ Wp,
                             const float* __restrict__ Wm) {
    __shared__ float sWi[32 * 97]; // transposed [k][r], padded
    __shared__ float sWh[32 * 97];
    __shared__ float sWp[32 * 40];
    __shared__ float sWm[40 * 40];
    int t = threadIdx.x;
    for (int i = t; i < 96 * 32; i += 256) {
        int r = i >> 5, k = i & 31;
        sWi[k * 97 + r] = wih[i];
        sWh[k * 97 + r] = whh[i];
    }
    for (int i = t; i < 32 * 40; i += 256) sWp[i] = Wp[i];
    for (int i = t; i < 40 * 40; i += 256) sWm[i] = Wm[i];
    __syncthreads();

    int node = blockIdx.x * 8 + (t >> 5);
    if (node >= N_NODES) return;
    int lane = t & 31;
    int idx = node * 32 + lane;
    float a  = g_agg1[idx];
    float hv = g_h1[idx];

    float gir = bih[lane], giz = bih[32 + lane], gin = bih[64 + lane];
    float ghr = bhh[lane], ghz = bhh[32 + lane], ghn = bhh[64 + lane];
#pragma unroll
    for (int k = 0; k < 32; k++) {
        float ak = __shfl_sync(0xffffffffu, a,  k);
        float hk = __shfl_sync(0xffffffffu, hv, k);
        const float* wi = &sWi[k * 97];
        const float* wh = &sWh[k * 97];
        gir = fmaf(ak, wi[lane],      gir);
        giz = fmaf(ak, wi[32 + lane], giz);
        gin = fmaf(ak, wi[64 + lane], gin);
        ghr = fmaf(hk, wh[lane],      ghr);
        ghz = fmaf(hk, wh[32 + lane], ghz);
        ghn = fmaf(hk, wh[64 + lane], ghn);
    }
    float r = 1.f / (1.f + __expf(-(gir + ghr)));
    float z = 1.f / (1.f + __expf(-(giz + ghz)));
    float n = tanhf(gin + r * ghn);
    float hr = fmaxf((1.f - z) * n + z * hv, 0.f);   // relu(gru1 out)

    // ---- proj2: h2 = hr@Wp (32->40), m2 = h2@Wm (40->40) ----
    int c2 = 32 + (lane & 7);
    float h_lo = 0.f, h_hi = 0.f;
#pragma unroll
    for (int k = 0; k < 32; k++) {
        float ak = __shfl_sync(0xffffffffu, hr, k);
        h_lo = fmaf(ak, sWp[k * 40 + lane], h_lo);
        h_hi = fmaf(ak, sWp[k * 40 + c2],   h_hi);
    }
    float m_lo = 0.f, m_hi = 0.f;
#pragma unroll
    for (int k = 0; k < 32; k++) {
        float hk = __shfl_sync(0xffffffffu, h_lo, k);
        m_lo = fmaf(hk, sWm[k * 40 + lane], m_lo);
        m_hi = fmaf(hk, sWm[k * 40 + c2],   m_hi);
    }
#pragma unroll
    for (int k = 0; k < 8; k++) {
        float hk = __shfl_sync(0xffffffffu, h_hi, k);
        m_lo = fmaf(hk, sWm[(32 + k) * 40 + lane], m_lo);
        m_hi = fmaf(hk, sWm[(32 + k) * 40 + c2],   m_hi);
    }
    int base = node * 40;
    g_h2[base + lane] = h_lo;
    g_m2[base + lane] = m_lo;
    g_agg2[base + lane] = 0.f;
    if (lane < 8) {
        g_h2[base + 32 + lane] = h_hi;
        g_m2[base + 32 + lane] = m_hi;
        g_agg2[base + 32 + lane] = 0.f;
    }
}

// ---------------- K4: edge scatter layer 2 — 10 threads/edge, float4 + red.v4 ----
__global__ void k_edge2(const int* __restrict__ ei,
                        const float* __restrict__ ew) {
    long long tid = (long long)blockIdx.x * blockDim.x + threadIdx.x;
    int e = (int)(tid / 10);
    if (e >= N_EDGES) return;
    int q = (int)(tid - (long long)e * 10);  // chunk 0..9 (40 floats)
    int src = ei[e];
    int dst = ei[N_EDGES + e];
    float w = ew[e];
    const float4* mrow = (const float4*)&g_m2[src * 40];
    float4 m = mrow[q];
    m.x *= w; m.y *= w; m.z *= w; m.w *= w;
    red_add_v4(&g_agg2[dst * 40 + q * 4], m);
}

// ---------------- K5: GRU cell layer 2 + log_softmax ----------------
__global__ void k_gru2(float* __restrict__ out,
                       const float* __restrict__ wih,
                       const float* __restrict__ whh,
                       const float* __restrict__ bih,
                       const float* __restrict__ bhh) {
    __shared__ float sWi[40 * 121]; // [k][r], padded stride 121
    __shared__ float sWh[40 * 121];
    int t = threadIdx.x;
    for (int i = t; i < 120 * 40; i += 256) {
        int r = i / 40, k = i % 40;
        sWi[k * 121 + r] = wih[i];
        sWh[k * 121 + r] = whh[i];
    }
    __syncthreads();

    int node = blockIdx.x * 8 + (t >> 5);
    if (node >= N_NODES) return;
    int lane = t & 31;
    int c2 = 32 + (lane & 7);
    int b = node * 40;

    float a_lo = g_agg2[b + lane];
    float h_lo = g_h2[b + lane];
    float a_hi = (lane < 8) ? g_agg2[b + 32 + lane] : 0.f;
    float h_hi = (lane < 8) ? g_h2[b + 32 + lane]   : 0.f;

    float gir = bih[lane], giz = bih[40 + lane], gin = bih[80 + lane];
    float ghr = bhh[lane], ghz = bhh[40 + lane], ghn = bhh[80 + lane];
    float gir2 = bih[c2], giz2 = bih[40 + c2], gin2 = bih[80 + c2];
    float ghr2 = bhh[c2], ghz2 = bhh[40 + c2], ghn2 = bhh[80 + c2];

#pragma unroll
    for (int k = 0; k < 40; k++) {
        float ak = (k < 32) ? __shfl_sync(0xffffffffu, a_lo, k)
                            : __shfl_sync(0xffffffffu, a_hi, k - 32);
        float hk = (k < 32) ? __shfl_sync(0xffffffffu, h_lo, k)
                            : __shfl_sync(0xffffffffu, h_hi, k - 32);
        const float* wi = &sWi[k * 121];
        const float* wh = &sWh[k * 121];
        gir  = fmaf(ak, wi[lane],      gir);
        giz  = fmaf(ak, wi[40 + lane], giz);
        gin  = fmaf(ak, wi[80 + lane], gin);
        gir2 = fmaf(ak, wi[c2],        gir2);
        giz2 = fmaf(ak, wi[40 + c2],   giz2);
        gin2 = fmaf(ak, wi[80 + c2],   gin2);
        ghr  = fmaf(hk, wh[lane],      ghr);
        ghz  = fmaf(hk, wh[40 + lane], ghz);
        ghn  = fmaf(hk, wh[80 + lane], ghn);
        ghr2 = fmaf(hk, wh[c2],        ghr2);
        ghz2 = fmaf(hk, wh[40 + c2],   ghz2);
        ghn2 = fmaf(hk, wh[80 + c2],   ghn2);
    }

    float r1 = 1.f / (1.f + __expf(-(gir + ghr)));
    float z1 = 1.f / (1.f + __expf(-(giz + ghz)));
    float n1 = tanhf(gin + r1 * ghn);
    float v1 = (1.f - z1) * n1 + z1 * h_lo;

    float r2 = 1.f / (1.f + __expf(-(gir2 + ghr2)));
    float z2 = 1.f / (1.f + __expf(-(giz2 + ghz2)));
    float n2 = tanhf(gin2 + r2 * ghn2);
    float v2 = (1.f - z2) * n2 + z2 * h_hi;

    float vmax = fmaxf(v1, (lane < 8) ? v2 : -FLT_MAX);
#pragma unroll
    for (int o = 16; o > 0; o >>= 1)
        vmax = fmaxf(vmax, __shfl_xor_sync(0xffffffffu, vmax, o));
    float se = __expf(v1 - vmax) + ((lane < 8) ? __expf(v2 - vmax) : 0.f);
#pragma unroll
    for (int o = 16; o > 0; o >>= 1)
        se += __shfl_xor_sync(0xffffffffu, se, o);
    float ls = vmax + logf(se);

    out[b + lane] = v1 - ls;
    if (lane < 8) out[b + 32 + lane] = v2 - ls;
}

// ---------------- launch ----------------
extern "C" void kernel_launch(void* const* d_in, const int* in_sizes, int n_in,
                              void* d_out, int out_size) {
    const float* x   = (const float*)d_in[0];
    const int*   ei  = (const int*)d_in[1];     // int32 (JAX x64 disabled)
    const float* ew  = (const float*)d_in[2];
    const float* W1p = (const float*)d_in[3];
    const float* W1m = (const float*)d_in[4];
    const float* g1wih = (const float*)d_in[5];
    const float* g1whh = (const float*)d_in[6];
    const float* g1bih = (const float*)d_in[7];
    const float* g1bhh = (const float*)d_in[8];
    const float* W2p = (const float*)d_in[9];
    const float* W2m = (const float*)d_in[10];
    const float* g2wih = (const float*)d_in[11];
    const float* g2whh = (const float*)d_in[12];
    const float* g2bih = (const float*)d_in[13];
    const float* g2bhh = (const float*)d_in[14];
    float* out = (float*)d_out;

    int nodeBlocks = (N_NODES + 7) / 8;
    k_proj1<<<nodeBlocks, 256>>>(x, W1p, W1m);

    long long th1 = (long long)N_EDGES * 8;
    k_edge1<<<(int)((th1 + 255) / 256), 256>>>(ei, ew);

    k_gru1_proj2<<<nodeBlocks, 256>>>(g1wih, g1whh, g1bih, g1bhh, W2p, W2m);

    long long th2 = (long long)N_EDGES * 10;
    k_edge2<<<(int)((th2 + 255) / 256), 256>>>(ei, ew);

    k_gru2<<<nodeBlocks, 256>>>(out, g2wih, g2whh, g2bih, g2bhh);
}

// round 6
// speedup vs baseline: 2.3732x; 1.6263x over previous
#include <cuda_runtime.h>
#include <cstdint>
#include <float.h>

#define N_NODES 100000
#define N_EDGES 2000000
#define HID 32
#define NCLS 40

// 100000 = 3125 * 32  -> 32 nodes per block (8 warps x 4 nodes), no tail.
#define NODE_BLOCKS 3125

// ---------------- scratch (static device memory; no allocation) ----------------
__device__ float g_h1 [N_NODES * HID];
__device__ float g_m1 [N_NODES * HID];
__device__ float g_agg1[N_NODES * HID];
__device__ float g_h2 [N_NODES * NCLS];
__device__ float g_m2 [N_NODES * NCLS];
__device__ float g_agg2[N_NODES * NCLS];

__device__ __forceinline__ void red_add_v4(float* addr, float4 v) {
    asm volatile("red.global.add.v4.f32 [%0], {%1,%2,%3,%4};"
                 :: "l"(addr), "f"(v.x), "f"(v.y), "f"(v.z), "f"(v.w)
                 : "memory");
}

// ---------------- K1: h1 = x@W1p, m1 = h1@W1m, zero agg1 (4 nodes/warp) --------
__global__ void __launch_bounds__(256) k_proj1(const float* __restrict__ x,
                        const float* __restrict__ Wp,
                        const float* __restrict__ Wm) {
    __shared__ float sWp[1024];
    __shared__ float sWm[1024];
    int t = threadIdx.x;
    for (int i = t; i < 1024; i += 256) { sWp[i] = Wp[i]; sWm[i] = Wm[i]; }
    __syncthreads();

    int lane = t & 31;
    int n0 = blockIdx.x * 32 + (t >> 5) * 4;

    float xv[4], h[4], m[4];
#pragma unroll
    for (int i = 0; i < 4; i++) { xv[i] = x[(n0 + i) * 32 + lane]; h[i] = 0.f; m[i] = 0.f; }

#pragma unroll
    for (int k = 0; k < 32; k++) {
        float w = sWp[k * 32 + lane];
#pragma unroll
        for (int i = 0; i < 4; i++)
            h[i] = fmaf(__shfl_sync(0xffffffffu, xv[i], k), w, h[i]);
    }
#pragma unroll
    for (int k = 0; k < 32; k++) {
        float w = sWm[k * 32 + lane];
#pragma unroll
        for (int i = 0; i < 4; i++)
            m[i] = fmaf(__shfl_sync(0xffffffffu, h[i], k), w, m[i]);
    }
#pragma unroll
    for (int i = 0; i < 4; i++) {
        int idx = (n0 + i) * 32 + lane;
        g_h1[idx] = h[i];
        g_m1[idx] = m[i];
        g_agg1[idx] = 0.f;
    }
}

// ---------------- K2: edge scatter layer 1 — 8 threads/edge, float4 + red.v4 ----
__global__ void k_edge1(const int* __restrict__ ei,
                        const float* __restrict__ ew) {
    long long tid = (long long)blockIdx.x * blockDim.x + threadIdx.x;
    int e = (int)(tid >> 3);
    if (e >= N_EDGES) return;
    int q = (int)(tid & 7);
    int src = ei[e];
    int dst = ei[N_EDGES + e];
    float w = ew[e];
    const float4* mrow = (const float4*)&g_m1[src * 32];
    float4 m = mrow[q];
    m.x *= w; m.y *= w; m.z *= w; m.w *= w;
    red_add_v4(&g_agg1[dst * 32 + q * 4], m);
}

// ------- K3: GRU1 + ReLU + proj2 + msg2 fused, zero agg2 (4 nodes/warp) --------
__global__ void __launch_bounds__(256) k_gru1_proj2(
                             const float* __restrict__ wih,
                             const float* __restrict__ whh,
                             const float* __restrict__ bih,
                             const float* __restrict__ bhh,
                             const float* __restrict__ Wp,
                             const float* __restrict__ Wm) {
    __shared__ float sWi[32 * 97]; // transposed [k][r], padded
    __shared__ float sWh[32 * 97];
    __shared__ float sWp[32 * 40];
    __shared__ float sWm[40 * 40];
    int t = threadIdx.x;
    for (int i = t; i < 96 * 32; i += 256) {
        int r = i >> 5, k = i & 31;
        sWi[k * 97 + r] = wih[i];
        sWh[k * 97 + r] = whh[i];
    }
    for (int i = t; i < 32 * 40; i += 256) sWp[i] = Wp[i];
    for (int i = t; i < 40 * 40; i += 256) sWm[i] = Wm[i];
    __syncthreads();

    int lane = t & 31;
    int n0 = blockIdx.x * 32 + (t >> 5) * 4;

    float a[4], hv[4];
    float gir[4], giz[4], gin[4], ghr[4], ghz[4], ghn[4];
    float b_ir = bih[lane], b_iz = bih[32 + lane], b_in = bih[64 + lane];
    float b_hr = bhh[lane], b_hz = bhh[32 + lane], b_hn = bhh[64 + lane];
#pragma unroll
    for (int i = 0; i < 4; i++) {
        int idx = (n0 + i) * 32 + lane;
        a[i] = g_agg1[idx];
        hv[i] = g_h1[idx];
        gir[i] = b_ir; giz[i] = b_iz; gin[i] = b_in;
        ghr[i] = b_hr; ghz[i] = b_hz; ghn[i] = b_hn;
    }

#pragma unroll 8
    for (int k = 0; k < 32; k++) {
        const float* wi = &sWi[k * 97];
        const float* wh = &sWh[k * 97];
        float wir = wi[lane], wiz = wi[32 + lane], win = wi[64 + lane];
        float whr = wh[lane], whz = wh[32 + lane], whn = wh[64 + lane];
#pragma unroll
        for (int i = 0; i < 4; i++) {
            float ak = __shfl_sync(0xffffffffu, a[i],  k);
            float hk = __shfl_sync(0xffffffffu, hv[i], k);
            gir[i] = fmaf(ak, wir, gir[i]);
            giz[i] = fmaf(ak, wiz, giz[i]);
            gin[i] = fmaf(ak, win, gin[i]);
            ghr[i] = fmaf(hk, whr, ghr[i]);
            ghz[i] = fmaf(hk, whz, ghz[i]);
            ghn[i] = fmaf(hk, whn, ghn[i]);
        }
    }

    float hr[4];
#pragma unroll
    for (int i = 0; i < 4; i++) {
        float r = 1.f / (1.f + __expf(-(gir[i] + ghr[i])));
        float z = 1.f / (1.f + __expf(-(giz[i] + ghz[i])));
        float n = tanhf(gin[i] + r * ghn[i]);
        hr[i] = fmaxf((1.f - z) * n + z * hv[i], 0.f);
    }

    // ---- proj2: h2 = hr@Wp (32->40), m2 = h2@Wm (40->40) ----
    int c2 = 32 + (lane & 7);
    float h_lo[4] = {0,0,0,0}, h_hi[4] = {0,0,0,0};
#pragma unroll 8
    for (int k = 0; k < 32; k++) {
        float wlo = sWp[k * 40 + lane];
        float whi = sWp[k * 40 + c2];
#pragma unroll
        for (int i = 0; i < 4; i++) {
            float ak = __shfl_sync(0xffffffffu, hr[i], k);
            h_lo[i] = fmaf(ak, wlo, h_lo[i]);
            h_hi[i] = fmaf(ak, whi, h_hi[i]);
        }
    }
    float m_lo[4] = {0,0,0,0}, m_hi[4] = {0,0,0,0};
#pragma unroll 8
    for (int k = 0; k < 32; k++) {
        float wlo = sWm[k * 40 + lane];
        float whi = sWm[k * 40 + c2];
#pragma unroll
        for (int i = 0; i < 4; i++) {
            float hk = __shfl_sync(0xffffffffu, h_lo[i], k);
            m_lo[i] = fmaf(hk, wlo, m_lo[i]);
            m_hi[i] = fmaf(hk, whi, m_hi[i]);
        }
    }
#pragma unroll
    for (int k = 0; k < 8; k++) {
        float wlo = sWm[(32 + k) * 40 + lane];
        float whi = sWm[(32 + k) * 40 + c2];
#pragma unroll
        for (int i = 0; i < 4; i++) {
            float hk = __shfl_sync(0xffffffffu, h_hi[i], k);
            m_lo[i] = fmaf(hk, wlo, m_lo[i]);
            m_hi[i] = fmaf(hk, whi, m_hi[i]);
        }
    }
#pragma unroll
    for (int i = 0; i < 4; i++) {
        int base = (n0 + i) * 40;
        g_h2[base + lane] = h_lo[i];
        g_m2[base + lane] = m_lo[i];
        g_agg2[base + lane] = 0.f;
        if (lane < 8) {
            g_h2[base + 32 + lane] = h_hi[i];
            g_m2[base + 32 + lane] = m_hi[i];
            g_agg2[base + 32 + lane] = 0.f;
        }
    }
}

// ---------------- K4: edge scatter layer 2 — 10 threads/edge, float4 + red.v4 ----
__global__ void k_edge2(const int* __restrict__ ei,
                        const float* __restrict__ ew) {
    long long tid = (long long)blockIdx.x * blockDim.x + threadIdx.x;
    int e = (int)(tid / 10);
    if (e >= N_EDGES) return;
    int q = (int)(tid - (long long)e * 10);
    int src = ei[e];
    int dst = ei[N_EDGES + e];
    float w = ew[e];
    const float4* mrow = (const float4*)&g_m2[src * 40];
    float4 m = mrow[q];
    m.x *= w; m.y *= w; m.z *= w; m.w *= w;
    red_add_v4(&g_agg2[dst * 40 + q * 4], m);
}

// ---------------- K5: GRU2 + log_softmax (4 nodes/warp) ----------------
__global__ void __launch_bounds__(256) k_gru2(float* __restrict__ out,
                       const float* __restrict__ wih,
                       const float* __restrict__ whh,
                       const float* __restrict__ bih,
                       const float* __restrict__ bhh) {
    __shared__ float sWi[40 * 121]; // [k][r], r in 0..119, padded stride 121
    __shared__ float sWh[40 * 121];
    int t = threadIdx.x;
    for (int i = t; i < 120 * 40; i += 256) {
        int r = i / 40, k = i % 40;
        sWi[k * 121 + r] = wih[i];
        sWh[k * 121 + r] = whh[i];
    }
    __syncthreads();

    int lane = t & 31;
    int c2 = 32 + (lane & 7);
    int n0 = blockIdx.x * 32 + (t >> 5) * 4;

    float a_lo[4], h_lo[4], a_hi[4], h_hi[4];
    float gir[4], giz[4], gin[4], ghr[4], ghz[4], ghn[4];
    float gir2[4], giz2[4], gin2[4], ghr2[4], ghz2[4], ghn2[4];
    {
        float b0 = bih[lane], b1 = bih[40 + lane], b2 = bih[80 + lane];
        float b3 = bhh[lane], b4 = bhh[40 + lane], b5 = bhh[80 + lane];
        float c0 = bih[c2], c1 = bih[40 + c2], c3 = bih[80 + c2];
        float c4 = bhh[c2], c5 = bhh[40 + c2], c6 = bhh[80 + c2];
#pragma unroll
        for (int i = 0; i < 4; i++) {
            int b = (n0 + i) * 40;
            a_lo[i] = g_agg2[b + lane];
            h_lo[i] = g_h2[b + lane];
            a_hi[i] = (lane < 8) ? g_agg2[b + 32 + lane] : 0.f;
            h_hi[i] = (lane < 8) ? g_h2[b + 32 + lane]   : 0.f;
            gir[i] = b0; giz[i] = b1; gin[i] = b2;
            ghr[i] = b3; ghz[i] = b4; ghn[i] = b5;
            gir2[i] = c0; giz2[i] = c1; gin2[i] = c3;
            ghr2[i] = c4; ghz2[i] = c5; ghn2[i] = c6;
        }
    }

#pragma unroll 4
    for (int k = 0; k < 32; k++) {
        const float* wi = &sWi[k * 121];
        const float* wh = &sWh[k * 121];
        float wi0 = wi[lane], wi1 = wi[40 + lane], wi2 = wi[80 + lane];
        float wj0 = wi[c2],   wj1 = wi[40 + c2],   wj2 = wi[80 + c2];
        float wh0 = wh[lane], wh1 = wh[40 + lane], wh2 = wh[80 + lane];
        float wg0 = wh[c2],   wg1 = wh[40 + c2],   wg2 = wh[80 + c2];
#pragma unroll
        for (int i = 0; i < 4; i++) {
            float ak = __shfl_sync(0xffffffffu, a_lo[i], k);
            float hk = __shfl_sync(0xffffffffu, h_lo[i], k);
            gir[i]  = fmaf(ak, wi0, gir[i]);
            giz[i]  = fmaf(ak, wi1, giz[i]);
            gin[i]  = fmaf(ak, wi2, gin[i]);
            gir2[i] = fmaf(ak, wj0, gir2[i]);
            giz2[i] = fmaf(ak, wj1, giz2[i]);
            gin2[i] = fmaf(ak, wj2, gin2[i]);
            ghr[i]  = fmaf(hk, wh0, ghr[i]);
            ghz[i]  = fmaf(hk, wh1, ghz[i]);
            ghn[i]  = fmaf(hk, wh2, ghn[i]);
            ghr2[i] = fmaf(hk, wg0, ghr2[i]);
            ghz2[i] = fmaf(hk, wg1, ghz2[i]);
            ghn2[i] = fmaf(hk, wg2, ghn2[i]);
        }
    }
#pragma unroll
    for (int k = 32; k < 40; k++) {
        const float* wi = &sWi[k * 121];
        const float* wh = &sWh[k * 121];
        float wi0 = wi[lane], wi1 = wi[40 + lane], wi2 = wi[80 + lane];
        float wj0 = wi[c2],   wj1 = wi[40 + c2],   wj2 = wi[80 + c2];
        float wh0 = wh[lane], wh1 = wh[40 + lane], wh2 = wh[80 + lane];
        float wg0 = wh[c2],   wg1 = wh[40 + c2],   wg2 = wh[80 + c2];
#pragma unroll
        for (int i = 0; i < 4; i++) {
            float ak = __shfl_sync(0xffffffffu, a_hi[i], k - 32);
            float hk = __shfl_sync(0xffffffffu, h_hi[i], k - 32);
            gir[i]  = fmaf(ak, wi0, gir[i]);
            giz[i]  = fmaf(ak, wi1, giz[i]);
            gin[i]  = fmaf(ak, wi2, gin[i]);
            gir2[i] = fmaf(ak, wj0, gir2[i]);
            giz2[i] = fmaf(ak, wj1, giz2[i]);
            gin2[i] = fmaf(ak, wj2, gin2[i]);
            ghr[i]  = fmaf(hk, wh0, ghr[i]);
            ghz[i]  = fmaf(hk, wh1, ghz[i]);
            ghn[i]  = fmaf(hk, wh2, ghn[i]);
            ghr2[i] = fmaf(hk, wg0, ghr2[i]);
            ghz2[i] = fmaf(hk, wg1, ghz2[i]);
            ghn2[i] = fmaf(hk, wg2, ghn2[i]);
        }
    }

#pragma unroll
    for (int i = 0; i < 4; i++) {
        float r1 = 1.f / (1.f + __expf(-(gir[i] + ghr[i])));
        float z1 = 1.f / (1.f + __expf(-(giz[i] + ghz[i])));
        float n1 = tanhf(gin[i] + r1 * ghn[i]);
        float v1 = (1.f - z1) * n1 + z1 * h_lo[i];

        float r2 = 1.f / (1.f + __expf(-(gir2[i] + ghr2[i])));
        float z2 = 1.f / (1.f + __expf(-(giz2[i] + ghz2[i])));
        float n2 = tanhf(gin2[i] + r2 * ghn2[i]);
        float v2 = (1.f - z2) * n2 + z2 * h_hi[i];

        float vmax = fmaxf(v1, (lane < 8) ? v2 : -FLT_MAX);
#pragma unroll
        for (int o = 16; o > 0; o >>= 1)
            vmax = fmaxf(vmax, __shfl_xor_sync(0xffffffffu, vmax, o));
        float se = __expf(v1 - vmax) + ((lane < 8) ? __expf(v2 - vmax) : 0.f);
#pragma unroll
        for (int o = 16; o > 0; o >>= 1)
            se += __shfl_xor_sync(0xffffffffu, se, o);
        float ls = vmax + logf(se);

        int b = (n0 + i) * 40;
        out[b + lane] = v1 - ls;
        if (lane < 8) out[b + 32 + lane] = v2 - ls;
    }
}

// ---------------- launch ----------------
extern "C" void kernel_launch(void* const* d_in, const int* in_sizes, int n_in,
                              void* d_out, int out_size) {
    const float* x   = (const float*)d_in[0];
    const int*   ei  = (const int*)d_in[1];     // int32 (JAX x64 disabled)
    const float* ew  = (const float*)d_in[2];
    const float* W1p = (const float*)d_in[3];
    const float* W1m = (const float*)d_in[4];
    const float* g1wih = (const float*)d_in[5];
    const float* g1whh = (const float*)d_in[6];
    const float* g1bih = (const float*)d_in[7];
    const float* g1bhh = (const float*)d_in[8];
    const float* W2p = (const float*)d_in[9];
    const float* W2m = (const float*)d_in[10];
    const float* g2wih = (const float*)d_in[11];
    const float* g2whh = (const float*)d_in[12];
    const float* g2bih = (const float*)d_in[13];
    const float* g2bhh = (const float*)d_in[14];
    float* out = (float*)d_out;

    k_proj1<<<NODE_BLOCKS, 256>>>(x, W1p, W1m);

    long long th1 = (long long)N_EDGES * 8;
    k_edge1<<<(int)((th1 + 255) / 256), 256>>>(ei, ew);

    k_gru1_proj2<<<NODE_BLOCKS, 256>>>(g1wih, g1whh, g1bih, g1bhh, W2p, W2m);

    long long th2 = (long long)N_EDGES * 10;
    k_edge2<<<(int)((th2 + 255) / 256), 256>>>(ei, ew);

    k_gru2<<<NODE_BLOCKS, 256>>>(out, g2wih, g2whh, g2bih, g2bhh);
}